// round 16
// baseline (speedup 1.0000x reference)
#include <cuda_runtime.h>
#include <cuda_fp16.h>
#include <math.h>
#include <stdint.h>

#define NHH  8
#define NN   1024
#define MM   21
#define CC   32
#define DD   84
#define BH   32
#define ROWS 86016
#define LOG2E 1.4426950408889634f

// ---- scratch (device globals) ----
__device__ __half g_q[(size_t)BH * NN * 96];    // [bh][n][d], q pre-scaled by log2e/32; d>=84 zero
__device__ __half g_k[(size_t)BH * NN * 96];
__device__ __half g_v[(size_t)BH * NN * 96];
__device__ float g_x2[BH * NN];
__device__ float g_pool[BH];
__device__ float g_part[64 * NN];
__device__ float g_table[NHH * 63 * 63];        // scaled by log2e
__device__ float g_opre[(size_t)ROWS * CC];

// ---- fp16 mma.sync: D(f32) += A(f16) * B(f16) ----
__device__ __forceinline__ void mma16816(float* c, uint32_t a0, uint32_t a1,
                                         uint32_t a2, uint32_t a3,
                                         uint32_t b0, uint32_t b1) {
    asm volatile(
        "mma.sync.aligned.m16n8k16.row.col.f32.f16.f16.f32 "
        "{%0,%1,%2,%3}, {%4,%5,%6,%7}, {%8,%9}, {%0,%1,%2,%3};"
        : "+f"(c[0]), "+f"(c[1]), "+f"(c[2]), "+f"(c[3])
        : "r"(a0), "r"(a1), "r"(a2), "r"(a3), "r"(b0), "r"(b1));
}

__device__ __forceinline__ uint32_t smem_u32(const void* p) {
    uint32_t a;
    asm("{ .reg .u64 t; cvta.to.shared.u64 t, %1; cvt.u32.u64 %0, t; }" : "=r"(a) : "l"(p));
    return a;
}
__device__ __forceinline__ void cpa16(uint32_t s, const void* g) {
    asm volatile("cp.async.cg.shared.global [%0], [%1], 16;" :: "r"(s), "l"(g));
}
__device__ __forceinline__ void cpa4(uint32_t s, const void* g) {
    asm volatile("cp.async.ca.shared.global [%0], [%1], 4;" :: "r"(s), "l"(g));
}
#define CP_COMMIT() asm volatile("cp.async.commit_group;" ::: "memory")

#define LDSM_X4(r0, r1, r2, r3, a) \
    asm volatile("ldmatrix.sync.aligned.m8n8.x4.shared.b16 {%0,%1,%2,%3}, [%4];" \
                 : "=r"(r0), "=r"(r1), "=r"(r2), "=r"(r3) : "r"(a))

// ---------------------------------------------------------------------------
// K1: qkv, register-blocked, chunk-split. Grid (336, 3); blockIdx.y = q/k/v.
//     One thread per (b_, m) row computing 32 outputs of its chunk.
// ---------------------------------------------------------------------------
__global__ void __launch_bounds__(256) k_qkv(const float* __restrict__ x,
                                             const float* __restrict__ Wq,
                                             const float* __restrict__ bq) {
    __shared__ float ws[32][32];
    __shared__ float bs[32];
    int t = threadIdx.x;
    int chunk = blockIdx.y;
    for (int i = t; i < 32 * 32; i += 256)
        ws[i >> 5][i & 31] = Wq[(i >> 5) * 96 + chunk * 32 + (i & 31)];
    if (t < 32) bs[t] = bq[chunk * 32 + t];
    __syncthreads();
    int R = blockIdx.x * 256 + t;        // < 86016
    float xv[32];
    const float4* xr = (const float4*)(x + (size_t)R * 32);
#pragma unroll
    for (int q = 0; q < 8; q++) {
        float4 v = xr[q];
        xv[4 * q] = v.x; xv[4 * q + 1] = v.y; xv[4 * q + 2] = v.z; xv[4 * q + 3] = v.w;
    }
    int b_ = R / 21, m = R - b_ * 21;
    int b = b_ >> 10, n = b_ & 1023;
    float acc[32];
#pragma unroll
    for (int jj = 0; jj < 32; jj++) acc[jj] = bs[jj];
#pragma unroll
    for (int kk = 0; kk < 32; kk++) {
        float xvk = xv[kk];
        const float4* wr = (const float4*)&ws[kk][0];
#pragma unroll
        for (int u = 0; u < 8; u++) {
            float4 wv = wr[u];
            acc[4 * u]     += xvk * wv.x;
            acc[4 * u + 1] += xvk * wv.y;
            acc[4 * u + 2] += xvk * wv.z;
            acc[4 * u + 3] += xvk * wv.w;
        }
    }
    float sc = (chunk == 0) ? (0.03125f * LOG2E) : 1.0f;
    __half* dst = (chunk == 0) ? g_q : ((chunk == 1) ? g_k : g_v);
#pragma unroll
    for (int hh = 0; hh < 8; hh++) {
        __half2 p0 = __float22half2_rn(make_float2(acc[hh * 4] * sc, acc[hh * 4 + 1] * sc));
        __half2 p1 = __float22half2_rn(make_float2(acc[hh * 4 + 2] * sc, acc[hh * 4 + 3] * sc));
        uint2 pk;
        pk.x = *(uint32_t*)&p0; pk.y = *(uint32_t*)&p1;
        size_t di = ((size_t)((((b << 3) | hh) << 10) | n)) * 96 + (m << 2);
        *(uint2*)&dst[di] = pk;
    }
    if (m == 20) {  // zero d-padding 84..95 for this n, all heads, this chunk
        uint2 z = make_uint2(0u, 0u);
#pragma unroll
        for (int hh = 0; hh < 8; hh++) {
            size_t di = ((size_t)((((b << 3) | hh) << 10) | n)) * 96 + 84;
            *(uint2*)&dst[di] = z;
            *(uint2*)&dst[di + 4] = z;
            *(uint2*)&dst[di + 8] = z;
        }
    }
}

// ---------------------------------------------------------------------------
// K2: x2[b,h,n]
// ---------------------------------------------------------------------------
__global__ void k_x2(const float* __restrict__ x, const float* __restrict__ Wsq,
                     const float* __restrict__ bsq) {
    __shared__ float w[DD];
    int t = threadIdx.x;
    if (t < DD) w[t] = Wsq[t];
    __syncthreads();
    int gid = blockIdx.x * blockDim.x + t;
    if (gid >= BH * NN) return;
    int n = gid & 1023;
    int bh = gid >> 10;
    int h = bh & 7, b = bh >> 3;
    const float* xr = x + (size_t)(b * NN + n) * (MM * CC) + h * 4;
    float acc = bsq[0];
#pragma unroll
    for (int m = 0; m < MM; m++)
#pragma unroll
        for (int c = 0; c < 4; c++) acc += xr[m * 32 + c] * w[m * 4 + c];
    g_x2[gid] = acc;
}

// ---------------------------------------------------------------------------
// K3: depthwise conv partials (+ fused pool on the o-even blocks)
// ---------------------------------------------------------------------------
__global__ void k_spatial_p(const float* __restrict__ Wdw) {
    int o = blockIdx.x >> 2, bb = blockIdx.x & 3, ic = o >> 1;
    __shared__ float xs[NN];
    __shared__ float wk[9];
    __shared__ float red[256], redm[256];
    int t = threadIdx.x;
    if (t < 9) wk[t] = Wdw[o * 9 + t];
    for (int i = t; i < NN; i += 256) xs[i] = g_x2[(size_t)(bb * 8 + ic) * NN + i];
    __syncthreads();
    if ((o & 1) == 0) {   // fused pool for plane (bb, h=o/2)
        float s = 0.f, mx = -1e30f;
        for (int i = t; i < NN; i += 256) { float v = xs[i]; s += v; mx = fmaxf(mx, v); }
        red[t] = s; redm[t] = mx;
        __syncthreads();
        for (int off = 128; off > 0; off >>= 1) {
            if (t < off) { red[t] += red[t + off]; redm[t] = fmaxf(redm[t], redm[t + off]); }
            __syncthreads();
        }
        if (t == 0) g_pool[bb * 8 + ic] = red[0] * (1.0f / 1024.0f) + redm[0];
    }
#pragma unroll
    for (int qq = 0; qq < 4; qq++) {
        int pix = qq * 256 + t;
        int y = pix >> 5, xx = pix & 31;
        float s = 0.f;
#pragma unroll
        for (int dy = -1; dy <= 1; dy++)
#pragma unroll
            for (int dx = -1; dx <= 1; dx++) {
                int yy = y + dy, xq = xx + dx;
                if (yy >= 0 && yy < 32 && xq >= 0 && xq < 32)
                    s += xs[yy * 32 + xq] * wk[(dy + 1) * 3 + (dx + 1)];
            }
        g_part[(size_t)blockIdx.x * NN + pix] = s;
    }
}

// ---------------------------------------------------------------------------
// K4: fused combine + correlation. Block (i, h) x 512 threads.
// ---------------------------------------------------------------------------
__global__ void __launch_bounds__(512) k_corrc(const float* __restrict__ bdw) {
    int i = blockIdx.x, h = blockIdx.y;
    int t = threadIdx.x;
    __shared__ float xp[NN], xw[NN];
    __shared__ float part[8][64];
    float ps = 0.25f * (g_pool[h] + g_pool[8 + h] + g_pool[16 + h] + g_pool[24 + h]);
    float bw = bdw[h] + ps, bp2 = bdw[8 + h] + ps;
    for (int idx = t; idx < NN; idx += 512) {
        float sw = 0.f, sp = 0.f;
#pragma unroll
        for (int bb = 0; bb < 4; bb++) {
            sw += g_part[(size_t)(h * 4 + bb) * NN + idx];
            sp += g_part[(size_t)((8 + h) * 4 + bb) * NN + idx];
        }
        xw[idx] = 0.25f * sw + bw;
        xp[idx] = 0.25f * sp + bp2;
    }
    __syncthreads();
    int j = t & 63, s = t >> 6;
    float acc = 0.f;
    if (j < 63) {
        int a0 = max(0, i - 31), a1 = min(31, i);
        int b0 = max(0, j - 31), b1 = min(31, j);
        for (int a = a0 + s; a <= a1; a += 8) {
            const float* rp = xp + (i - a) * 32 + j;
            const float* rw = xw + a * 32;
#pragma unroll 4
            for (int b = b0; b <= b1; b++) acc += rp[-b] * rw[b];
        }
    }
    part[s][j] = acc;
    __syncthreads();
    if (t < 63) {
        float total = 0.f;
#pragma unroll
        for (int q = 0; q < 8; q++) total += part[q][t];
        g_table[h * 3969 + i * 63 + t] = total * LOG2E;
    }
}

// ---------------------------------------------------------------------------
// K5: fused flash attention (base-2 softmax); 64-row kv chunks double buffered.
// ---------------------------------------------------------------------------
#define FL_KOFF(s) (26624 + (s) * 13312)
#define FL_VOFF(s) (53248 + (s) * 13312)
#define FL_TOFF(s) (79872 + (s) * 1264)
#define FL_SMEM    82400

__device__ __forceinline__ void cpa_tile(uint32_t dstb, const __half* __restrict__ g,
                                         int tid, int nch) {
    for (int i = tid; i < nch; i += 256) {
        int r = i / 12, q = i - r * 12;
        cpa16(dstb + r * 208 + q * 16, g + r * 96 + q * 8);
    }
}

__global__ void __launch_bounds__(256, 2) k_flash() {
    extern __shared__ char smem[];
    uint32_t sb = smem_u32(smem);
    const int tid = threadIdx.x, w = tid >> 5, lane = tid & 31;
    const int g = lane >> 2, tq = lane & 3;
    const int It = blockIdx.x, bh = blockIdx.y, h = bh & 7;
    const int rt = It * 128;
    const int ri5 = w >> 1;
    const int ra0 = (w & 1) * 16 + g;
    const __half* kbase = g_k + ((size_t)bh << 10) * 96;
    const __half* vbase = g_v + ((size_t)bh << 10) * 96;
    const float* tbase = g_table + h * 3969;

    const int lmA_row = lane & 15, lmA_cg = (lane >> 4) << 3;
    const int lmB_row = ((lane >> 4) << 3) + (lane & 7);
    const int lmB_cg = ((lane >> 3) & 1) << 3;
    const int lm_row = lane & 15;
    const int lm_col = (lane >> 4) << 3;

    cpa_tile(sb, g_q + ((size_t)(bh << 10) + rt) * 96, tid, 1536);
    cpa_tile(sb + FL_KOFF(0), kbase, tid, 768);
    cpa_tile(sb + FL_VOFF(0), vbase, tid, 768);
    {
        const float* tg = tbase + (4 * It + 30) * 63;
        for (int i = tid; i < 315; i += 256) cpa4(sb + FL_TOFF(0) + i * 4, tg + i);
    }
    CP_COMMIT();

    float m0 = -1e30f, m1 = -1e30f, l0 = 0.f, l1 = 0.f;
    float oacc[11][4];
#pragma unroll
    for (int j = 0; j < 11; j++)
#pragma unroll
        for (int e = 0; e < 4; e++) oacc[j][e] = 0.f;

#pragma unroll 1
    for (int nb = 0; nb < 16; nb++) {
        __syncthreads();
        if (nb < 15) {
            int s = (nb + 1) & 1;
            cpa_tile(sb + FL_KOFF(s), kbase + (size_t)(nb + 1) * 64 * 96, tid, 768);
            cpa_tile(sb + FL_VOFF(s), vbase + (size_t)(nb + 1) * 64 * 96, tid, 768);
            const float* tg = tbase + (4 * It - 2 * (nb + 1) + 30) * 63;
            for (int i = tid; i < 315; i += 256) cpa4(sb + FL_TOFF(s) + i * 4, tg + i);
            CP_COMMIT();
            asm volatile("cp.async.wait_group 1;" ::: "memory");
        } else {
            asm volatile("cp.async.wait_group 0;" ::: "memory");
        }
        __syncthreads();

        const uint32_t ksb = sb + FL_KOFF(nb & 1);
        const uint32_t vsb = sb + FL_VOFF(nb & 1);
        const float* tabs = (const float*)(smem + FL_TOFF(nb & 1));

        float sacc[8][4];
#pragma unroll
        for (int j = 0; j < 8; j++)
#pragma unroll
            for (int e = 0; e < 4; e++) sacc[j][e] = 0.f;

#pragma unroll
        for (int ks = 0; ks < 6; ks++) {
            int k0 = ks * 16;
            uint32_t a0, a1, a2, a3;
            uint32_t qa = sb + (uint32_t)((w * 16 + lmA_row) * 208 + (k0 + lmA_cg) * 2);
            LDSM_X4(a0, a1, a2, a3, qa);
#pragma unroll
            for (int jp = 0; jp < 4; jp++) {
                uint32_t r0, r1, r2, r3;
                uint32_t ka = ksb + (uint32_t)((jp * 16 + lmB_row) * 208 + (k0 + lmB_cg) * 2);
                LDSM_X4(r0, r1, r2, r3, ka);
                mma16816(sacc[2 * jp], a0, a1, a2, a3, r0, r1);
                mma16816(sacc[2 * jp + 1], a0, a1, a2, a3, r2, r3);
            }
        }

        float rmax0 = -1e30f, rmax1 = -1e30f;
#pragma unroll
        for (int j = 0; j < 8; j++) {
            int jl = j * 8 + 2 * tq;
            int rj5 = jl >> 5, cj = jl & 31;
            int dR0 = (ri5 - rj5 + 1) * 63;
            sacc[j][0] += tabs[dR0 + ra0 - cj + 31];
            sacc[j][1] += tabs[dR0 + ra0 - cj + 30];
            sacc[j][2] += tabs[dR0 + ra0 + 8 - cj + 31];
            sacc[j][3] += tabs[dR0 + ra0 + 8 - cj + 30];
            rmax0 = fmaxf(rmax0, fmaxf(sacc[j][0], sacc[j][1]));
            rmax1 = fmaxf(rmax1, fmaxf(sacc[j][2], sacc[j][3]));
        }
        rmax0 = fmaxf(rmax0, __shfl_xor_sync(0xffffffffu, rmax0, 1));
        rmax0 = fmaxf(rmax0, __shfl_xor_sync(0xffffffffu, rmax0, 2));
        rmax1 = fmaxf(rmax1, __shfl_xor_sync(0xffffffffu, rmax1, 1));
        rmax1 = fmaxf(rmax1, __shfl_xor_sync(0xffffffffu, rmax1, 2));

        float mn0 = fmaxf(m0, rmax0), mn1 = fmaxf(m1, rmax1);
        float al0 = exp2f(m0 - mn0), al1 = exp2f(m1 - mn1);
        m0 = mn0; m1 = mn1;
        float ls0 = 0.f, ls1 = 0.f;
#pragma unroll
        for (int j = 0; j < 8; j++) {
            sacc[j][0] = exp2f(sacc[j][0] - mn0);
            sacc[j][1] = exp2f(sacc[j][1] - mn0);
            sacc[j][2] = exp2f(sacc[j][2] - mn1);
            sacc[j][3] = exp2f(sacc[j][3] - mn1);
            ls0 += sacc[j][0] + sacc[j][1];
            ls1 += sacc[j][2] + sacc[j][3];
        }
        l0 = l0 * al0 + ls0;
        l1 = l1 * al1 + ls1;
#pragma unroll
        for (int j = 0; j < 11; j++) {
            oacc[j][0] *= al0; oacc[j][1] *= al0;
            oacc[j][2] *= al1; oacc[j][3] *= al1;
        }

#pragma unroll
        for (int kk = 0; kk < 4; kk++) {
            __half2 h0 = __float22half2_rn(make_float2(sacc[2 * kk][0], sacc[2 * kk][1]));
            __half2 h1 = __float22half2_rn(make_float2(sacc[2 * kk][2], sacc[2 * kk][3]));
            __half2 h2 = __float22half2_rn(make_float2(sacc[2 * kk + 1][0], sacc[2 * kk + 1][1]));
            __half2 h3 = __float22half2_rn(make_float2(sacc[2 * kk + 1][2], sacc[2 * kk + 1][3]));
            uint32_t a0 = *(uint32_t*)&h0, a1 = *(uint32_t*)&h1;
            uint32_t a2 = *(uint32_t*)&h2, a3 = *(uint32_t*)&h3;
            int k0 = kk * 16;
            uint32_t rowaddr = vsb + (uint32_t)((k0 + lm_row) * 208);
#pragma unroll
            for (int jj = 0; jj < 6; jj++) {
                uint32_t r0, r1, r2, r3;
                uint32_t a = rowaddr + (uint32_t)((jj * 16 + lm_col) * 2);
                asm volatile(
                    "ldmatrix.sync.aligned.m8n8.x4.trans.shared.b16 {%0,%1,%2,%3}, [%4];"
                    : "=r"(r0), "=r"(r1), "=r"(r2), "=r"(r3) : "r"(a));
                mma16816(oacc[2 * jj], a0, a1, a2, a3, r0, r1);
                if (jj < 5) mma16816(oacc[2 * jj + 1], a0, a1, a2, a3, r2, r3);
            }
        }
    }

    l0 += __shfl_xor_sync(0xffffffffu, l0, 1);
    l0 += __shfl_xor_sync(0xffffffffu, l0, 2);
    l1 += __shfl_xor_sync(0xffffffffu, l1, 1);
    l1 += __shfl_xor_sync(0xffffffffu, l1, 2);
    float inv0 = 1.f / l0, inv1 = 1.f / l1;
    int b = bh >> 3;
    int row0 = rt + w * 16 + g, row1 = row0 + 8;
#pragma unroll
    for (int j = 0; j < 11; j++) {
        int d = j * 8 + 2 * tq;
        if (d < DD) {
            int m = d >> 2, c = d & 3;
            size_t o0 = ((size_t)((b << 10) + row0) * 21 + m) * 32 + (h << 2) + c;
            size_t o1 = ((size_t)((b << 10) + row1) * 21 + m) * 32 + (h << 2) + c;
            *(float2*)&g_opre[o0] = make_float2(oacc[j][0] * inv0, oacc[j][1] * inv0);
            *(float2*)&g_opre[o1] = make_float2(oacc[j][2] * inv1, oacc[j][3] * inv1);
        }
    }
}

// ---------------------------------------------------------------------------
// K6: proj, register-blocked.
// ---------------------------------------------------------------------------
__global__ void __launch_bounds__(256) k_proj(const float* __restrict__ Wp,
                                              const float* __restrict__ bp,
                                              float* __restrict__ out) {
    __shared__ float ws[32][32];
    __shared__ float bs[32];
    int t = threadIdx.x;
    for (int i = t; i < 1024; i += 256) ws[i >> 5][i & 31] = Wp[i];
    if (t < 32) bs[t] = bp[t];
    __syncthreads();
    int R = blockIdx.x * 256 + t;
    float xv[32];
    const float4* xr = (const float4*)(g_opre + (size_t)R * 32);
#pragma unroll
    for (int q = 0; q < 8; q++) {
        float4 v = xr[q];
        xv[4 * q] = v.x; xv[4 * q + 1] = v.y; xv[4 * q + 2] = v.z; xv[4 * q + 3] = v.w;
    }
#pragma unroll
    for (int half = 0; half < 2; half++) {
        float acc[16];
#pragma unroll
        for (int jj = 0; jj < 16; jj++) acc[jj] = bs[half * 16 + jj];
#pragma unroll
        for (int kk = 0; kk < 32; kk++) {
            float xvk = xv[kk];
            const float4* wr = (const float4*)&ws[kk][half * 16];
#pragma unroll
            for (int u = 0; u < 4; u++) {
                float4 wv = wr[u];
                acc[4 * u]     += xvk * wv.x;
                acc[4 * u + 1] += xvk * wv.y;
                acc[4 * u + 2] += xvk * wv.z;
                acc[4 * u + 3] += xvk * wv.w;
            }
        }
        float4* orow = (float4*)(out + (size_t)R * 32 + half * 16);
#pragma unroll
        for (int u = 0; u < 4; u++)
            orow[u] = make_float4(acc[4 * u], acc[4 * u + 1], acc[4 * u + 2], acc[4 * u + 3]);
    }
}

// ---------------------------------------------------------------------------
extern "C" void kernel_launch(void* const* d_in, const int* in_sizes, int n_in,
                              void* d_out, int out_size) {
    (void)in_sizes; (void)n_in; (void)out_size;
    const float* x   = (const float*)d_in[0];
    const float* Wq  = (const float*)d_in[1];
    const float* bq  = (const float*)d_in[2];
    const float* Wp  = (const float*)d_in[3];
    const float* bp  = (const float*)d_in[4];
    const float* Wsq = (const float*)d_in[5];
    const float* bsq = (const float*)d_in[6];
    const float* Wdw = (const float*)d_in[7];
    const float* bdw = (const float*)d_in[8];
    float* out = (float*)d_out;

    static int init_done = 0;
    static cudaStream_t s2;
    static cudaEvent_t ev0, ev1;
    if (!init_done) {
        cudaFuncSetAttribute(k_flash, cudaFuncAttributeMaxDynamicSharedMemorySize, FL_SMEM);
        cudaStreamCreateWithFlags(&s2, cudaStreamNonBlocking);
        cudaEventCreateWithFlags(&ev0, cudaEventDisableTiming);
        cudaEventCreateWithFlags(&ev1, cudaEventDisableTiming);
        init_done = 1;
    }

    // Fork: bias chain on s2 runs concurrently with qkv on the main stream.
    cudaEventRecord(ev0, 0);
    cudaStreamWaitEvent(s2, ev0, 0);
    k_x2<<<128, 256, 0, s2>>>(x, Wsq, bsq);
    k_spatial_p<<<64, 256, 0, s2>>>(Wdw);
    k_corrc<<<dim3(63, NHH), 512, 0, s2>>>(bdw);
    cudaEventRecord(ev1, s2);

    k_qkv<<<dim3(336, 3), 256>>>(x, Wq, bq);

    // Join: flash needs q/k/v (stream order) and the bias table (ev1).
    cudaStreamWaitEvent(0, ev1, 0);
    k_flash<<<dim3(8, BH), 256, FL_SMEM>>>();
    k_proj<<<ROWS / 256, 256>>>(Wp, bp, out);
}

// round 17
// speedup vs baseline: 1.0426x; 1.0426x over previous
#include <cuda_runtime.h>
#include <cuda_fp16.h>
#include <math.h>
#include <stdint.h>

#define NHH  8
#define NN   1024
#define MM   21
#define CC   32
#define DD   84
#define BH   32
#define ROWS 86016
#define LOG2E 1.4426950408889634f

// ---- scratch (device globals) ----
__device__ __half g_q[(size_t)BH * NN * 96];    // [bh][n][d], q pre-scaled by log2e/32; d>=84 zero
__device__ __half g_k[(size_t)BH * NN * 96];
__device__ __half g_v[(size_t)BH * NN * 96];
__device__ float g_x2[BH * NN];
__device__ float g_pool[BH];
__device__ float g_part[64 * NN];
__device__ float g_table[NHH * 63 * 63];        // scaled by log2e
__device__ float g_opre[(size_t)ROWS * CC];

// ---- fp16 mma.sync: D(f32) += A(f16) * B(f16) ----
__device__ __forceinline__ void mma16816(float* c, uint32_t a0, uint32_t a1,
                                         uint32_t a2, uint32_t a3,
                                         uint32_t b0, uint32_t b1) {
    asm volatile(
        "mma.sync.aligned.m16n8k16.row.col.f32.f16.f16.f32 "
        "{%0,%1,%2,%3}, {%4,%5,%6,%7}, {%8,%9}, {%0,%1,%2,%3};"
        : "+f"(c[0]), "+f"(c[1]), "+f"(c[2]), "+f"(c[3])
        : "r"(a0), "r"(a1), "r"(a2), "r"(a3), "r"(b0), "r"(b1));
}

__device__ __forceinline__ uint32_t smem_u32(const void* p) {
    uint32_t a;
    asm("{ .reg .u64 t; cvta.to.shared.u64 t, %1; cvt.u32.u64 %0, t; }" : "=r"(a) : "l"(p));
    return a;
}
__device__ __forceinline__ void cpa16(uint32_t s, const void* g) {
    asm volatile("cp.async.cg.shared.global [%0], [%1], 16;" :: "r"(s), "l"(g));
}
__device__ __forceinline__ void cpa4(uint32_t s, const void* g) {
    asm volatile("cp.async.ca.shared.global [%0], [%1], 4;" :: "r"(s), "l"(g));
}
#define CP_COMMIT() asm volatile("cp.async.commit_group;" ::: "memory")

#define LDSM_X4(r0, r1, r2, r3, a) \
    asm volatile("ldmatrix.sync.aligned.m8n8.x4.shared.b16 {%0,%1,%2,%3}, [%4];" \
                 : "=r"(r0), "=r"(r1), "=r"(r2), "=r"(r3) : "r"(a))

// ---------------------------------------------------------------------------
// K1: qkv, register-blocked, single pass over chunks; reg-capped for 2 CTAs/SM.
//     One thread per (b_, m) row; 336 blocks x 256.
// ---------------------------------------------------------------------------
__global__ void __launch_bounds__(256, 2) k_qkv(const float* __restrict__ x,
                                                const float* __restrict__ Wq,
                                                const float* __restrict__ bq) {
    __shared__ float ws[32][96];
    __shared__ float bs[96];
    int t = threadIdx.x;
    for (int i = t; i < 32 * 96; i += 256) ws[i / 96][i % 96] = Wq[i];
    if (t < 96) bs[t] = bq[t];
    __syncthreads();
    int R = blockIdx.x * 256 + t;        // < 86016
    float xv[32];
    const float4* xr = (const float4*)(x + (size_t)R * 32);
#pragma unroll
    for (int q = 0; q < 8; q++) {
        float4 v = xr[q];
        xv[4 * q] = v.x; xv[4 * q + 1] = v.y; xv[4 * q + 2] = v.z; xv[4 * q + 3] = v.w;
    }
    int b_ = R / 21, m = R - b_ * 21;
    int b = b_ >> 10, n = b_ & 1023;
#pragma unroll 1
    for (int chunk = 0; chunk < 3; chunk++) {
        float acc[32];
#pragma unroll
        for (int jj = 0; jj < 32; jj++) acc[jj] = bs[chunk * 32 + jj];
#pragma unroll
        for (int kk = 0; kk < 32; kk++) {
            float xvk = xv[kk];
            const float4* wr = (const float4*)&ws[kk][chunk * 32];
#pragma unroll
            for (int u = 0; u < 8; u++) {
                float4 wv = wr[u];
                acc[4 * u]     += xvk * wv.x;
                acc[4 * u + 1] += xvk * wv.y;
                acc[4 * u + 2] += xvk * wv.z;
                acc[4 * u + 3] += xvk * wv.w;
            }
        }
        float sc = (chunk == 0) ? (0.03125f * LOG2E) : 1.0f;
        __half* dst = (chunk == 0) ? g_q : ((chunk == 1) ? g_k : g_v);
#pragma unroll
        for (int hh = 0; hh < 8; hh++) {
            __half2 p0 = __float22half2_rn(make_float2(acc[hh * 4] * sc, acc[hh * 4 + 1] * sc));
            __half2 p1 = __float22half2_rn(make_float2(acc[hh * 4 + 2] * sc, acc[hh * 4 + 3] * sc));
            uint2 pk;
            pk.x = *(uint32_t*)&p0; pk.y = *(uint32_t*)&p1;
            size_t di = ((size_t)((((b << 3) | hh) << 10) | n)) * 96 + (m << 2);
            *(uint2*)&dst[di] = pk;
        }
        if (m == 20) {  // zero d-padding 84..95
            uint2 z = make_uint2(0u, 0u);
#pragma unroll
            for (int hh = 0; hh < 8; hh++) {
                size_t di = ((size_t)((((b << 3) | hh) << 10) | n)) * 96 + 84;
                *(uint2*)&dst[di] = z;
                *(uint2*)&dst[di + 4] = z;
                *(uint2*)&dst[di + 8] = z;
            }
        }
    }
}

// ---------------------------------------------------------------------------
// K2: x2[b,h,n]
// ---------------------------------------------------------------------------
__global__ void k_x2(const float* __restrict__ x, const float* __restrict__ Wsq,
                     const float* __restrict__ bsq) {
    __shared__ float w[DD];
    int t = threadIdx.x;
    if (t < DD) w[t] = Wsq[t];
    __syncthreads();
    int gid = blockIdx.x * blockDim.x + t;
    if (gid >= BH * NN) return;
    int n = gid & 1023;
    int bh = gid >> 10;
    int h = bh & 7, b = bh >> 3;
    const float* xr = x + (size_t)(b * NN + n) * (MM * CC) + h * 4;
    float acc = bsq[0];
#pragma unroll
    for (int m = 0; m < MM; m++)
#pragma unroll
        for (int c = 0; c < 4; c++) acc += xr[m * 32 + c] * w[m * 4 + c];
    g_x2[gid] = acc;
}

// ---------------------------------------------------------------------------
// K3: depthwise conv partials (+ fused pool on the o-even blocks)
// ---------------------------------------------------------------------------
__global__ void k_spatial_p(const float* __restrict__ Wdw) {
    int o = blockIdx.x >> 2, bb = blockIdx.x & 3, ic = o >> 1;
    __shared__ float xs[NN];
    __shared__ float wk[9];
    __shared__ float red[256], redm[256];
    int t = threadIdx.x;
    if (t < 9) wk[t] = Wdw[o * 9 + t];
    for (int i = t; i < NN; i += 256) xs[i] = g_x2[(size_t)(bb * 8 + ic) * NN + i];
    __syncthreads();
    if ((o & 1) == 0) {   // fused pool for plane (bb, h=o/2)
        float s = 0.f, mx = -1e30f;
        for (int i = t; i < NN; i += 256) { float v = xs[i]; s += v; mx = fmaxf(mx, v); }
        red[t] = s; redm[t] = mx;
        __syncthreads();
        for (int off = 128; off > 0; off >>= 1) {
            if (t < off) { red[t] += red[t + off]; redm[t] = fmaxf(redm[t], redm[t + off]); }
            __syncthreads();
        }
        if (t == 0) g_pool[bb * 8 + ic] = red[0] * (1.0f / 1024.0f) + redm[0];
    }
#pragma unroll
    for (int qq = 0; qq < 4; qq++) {
        int pix = qq * 256 + t;
        int y = pix >> 5, xx = pix & 31;
        float s = 0.f;
#pragma unroll
        for (int dy = -1; dy <= 1; dy++)
#pragma unroll
            for (int dx = -1; dx <= 1; dx++) {
                int yy = y + dy, xq = xx + dx;
                if (yy >= 0 && yy < 32 && xq >= 0 && xq < 32)
                    s += xs[yy * 32 + xq] * wk[(dy + 1) * 3 + (dx + 1)];
            }
        g_part[(size_t)blockIdx.x * NN + pix] = s;
    }
}

// ---------------------------------------------------------------------------
// K4: fused combine + correlation. Block (i, h) x 512 threads.
// ---------------------------------------------------------------------------
__global__ void __launch_bounds__(512) k_corrc(const float* __restrict__ bdw) {
    int i = blockIdx.x, h = blockIdx.y;
    int t = threadIdx.x;
    __shared__ float xp[NN], xw[NN];
    __shared__ float part[8][64];
    float ps = 0.25f * (g_pool[h] + g_pool[8 + h] + g_pool[16 + h] + g_pool[24 + h]);
    float bw = bdw[h] + ps, bp2 = bdw[8 + h] + ps;
    for (int idx = t; idx < NN; idx += 512) {
        float sw = 0.f, sp = 0.f;
#pragma unroll
        for (int bb = 0; bb < 4; bb++) {
            sw += g_part[(size_t)(h * 4 + bb) * NN + idx];
            sp += g_part[(size_t)((8 + h) * 4 + bb) * NN + idx];
        }
        xw[idx] = 0.25f * sw + bw;
        xp[idx] = 0.25f * sp + bp2;
    }
    __syncthreads();
    int j = t & 63, s = t >> 6;
    float acc = 0.f;
    if (j < 63) {
        int a0 = max(0, i - 31), a1 = min(31, i);
        int b0 = max(0, j - 31), b1 = min(31, j);
        for (int a = a0 + s; a <= a1; a += 8) {
            const float* rp = xp + (i - a) * 32 + j;
            const float* rw = xw + a * 32;
#pragma unroll 4
            for (int b = b0; b <= b1; b++) acc += rp[-b] * rw[b];
        }
    }
    part[s][j] = acc;
    __syncthreads();
    if (t < 63) {
        float total = 0.f;
#pragma unroll
        for (int q = 0; q < 8; q++) total += part[q][t];
        g_table[h * 3969 + i * 63 + t] = total * LOG2E;
    }
}

// ---------------------------------------------------------------------------
// K5: fused flash attention (base-2 softmax); 64-row kv chunks double buffered.
// ---------------------------------------------------------------------------
#define FL_KOFF(s) (26624 + (s) * 13312)
#define FL_VOFF(s) (53248 + (s) * 13312)
#define FL_TOFF(s) (79872 + (s) * 1264)
#define FL_SMEM    82400

__device__ __forceinline__ void cpa_tile(uint32_t dstb, const __half* __restrict__ g,
                                         int tid, int nch) {
    for (int i = tid; i < nch; i += 256) {
        int r = i / 12, q = i - r * 12;
        cpa16(dstb + r * 208 + q * 16, g + r * 96 + q * 8);
    }
}

__global__ void __launch_bounds__(256, 2) k_flash() {
    extern __shared__ char smem[];
    uint32_t sb = smem_u32(smem);
    const int tid = threadIdx.x, w = tid >> 5, lane = tid & 31;
    const int g = lane >> 2, tq = lane & 3;
    const int It = blockIdx.x, bh = blockIdx.y, h = bh & 7;
    const int rt = It * 128;
    const int ri5 = w >> 1;
    const int ra0 = (w & 1) * 16 + g;
    const __half* kbase = g_k + ((size_t)bh << 10) * 96;
    const __half* vbase = g_v + ((size_t)bh << 10) * 96;
    const float* tbase = g_table + h * 3969;

    const int lmA_row = lane & 15, lmA_cg = (lane >> 4) << 3;
    const int lmB_row = ((lane >> 4) << 3) + (lane & 7);
    const int lmB_cg = ((lane >> 3) & 1) << 3;
    const int lm_row = lane & 15;
    const int lm_col = (lane >> 4) << 3;

    cpa_tile(sb, g_q + ((size_t)(bh << 10) + rt) * 96, tid, 1536);
    cpa_tile(sb + FL_KOFF(0), kbase, tid, 768);
    cpa_tile(sb + FL_VOFF(0), vbase, tid, 768);
    {
        const float* tg = tbase + (4 * It + 30) * 63;
        for (int i = tid; i < 315; i += 256) cpa4(sb + FL_TOFF(0) + i * 4, tg + i);
    }
    CP_COMMIT();

    float m0 = -1e30f, m1 = -1e30f, l0 = 0.f, l1 = 0.f;
    float oacc[11][4];
#pragma unroll
    for (int j = 0; j < 11; j++)
#pragma unroll
        for (int e = 0; e < 4; e++) oacc[j][e] = 0.f;

#pragma unroll 1
    for (int nb = 0; nb < 16; nb++) {
        __syncthreads();
        if (nb < 15) {
            int s = (nb + 1) & 1;
            cpa_tile(sb + FL_KOFF(s), kbase + (size_t)(nb + 1) * 64 * 96, tid, 768);
            cpa_tile(sb + FL_VOFF(s), vbase + (size_t)(nb + 1) * 64 * 96, tid, 768);
            const float* tg = tbase + (4 * It - 2 * (nb + 1) + 30) * 63;
            for (int i = tid; i < 315; i += 256) cpa4(sb + FL_TOFF(s) + i * 4, tg + i);
            CP_COMMIT();
            asm volatile("cp.async.wait_group 1;" ::: "memory");
        } else {
            asm volatile("cp.async.wait_group 0;" ::: "memory");
        }
        __syncthreads();

        const uint32_t ksb = sb + FL_KOFF(nb & 1);
        const uint32_t vsb = sb + FL_VOFF(nb & 1);
        const float* tabs = (const float*)(smem + FL_TOFF(nb & 1));

        float sacc[8][4];
#pragma unroll
        for (int j = 0; j < 8; j++)
#pragma unroll
            for (int e = 0; e < 4; e++) sacc[j][e] = 0.f;

#pragma unroll
        for (int ks = 0; ks < 6; ks++) {
            int k0 = ks * 16;
            uint32_t a0, a1, a2, a3;
            uint32_t qa = sb + (uint32_t)((w * 16 + lmA_row) * 208 + (k0 + lmA_cg) * 2);
            LDSM_X4(a0, a1, a2, a3, qa);
#pragma unroll
            for (int jp = 0; jp < 4; jp++) {
                uint32_t r0, r1, r2, r3;
                uint32_t ka = ksb + (uint32_t)((jp * 16 + lmB_row) * 208 + (k0 + lmB_cg) * 2);
                LDSM_X4(r0, r1, r2, r3, ka);
                mma16816(sacc[2 * jp], a0, a1, a2, a3, r0, r1);
                mma16816(sacc[2 * jp + 1], a0, a1, a2, a3, r2, r3);
            }
        }

        float rmax0 = -1e30f, rmax1 = -1e30f;
#pragma unroll
        for (int j = 0; j < 8; j++) {
            int jl = j * 8 + 2 * tq;
            int rj5 = jl >> 5, cj = jl & 31;
            int dR0 = (ri5 - rj5 + 1) * 63;
            sacc[j][0] += tabs[dR0 + ra0 - cj + 31];
            sacc[j][1] += tabs[dR0 + ra0 - cj + 30];
            sacc[j][2] += tabs[dR0 + ra0 + 8 - cj + 31];
            sacc[j][3] += tabs[dR0 + ra0 + 8 - cj + 30];
            rmax0 = fmaxf(rmax0, fmaxf(sacc[j][0], sacc[j][1]));
            rmax1 = fmaxf(rmax1, fmaxf(sacc[j][2], sacc[j][3]));
        }
        rmax0 = fmaxf(rmax0, __shfl_xor_sync(0xffffffffu, rmax0, 1));
        rmax0 = fmaxf(rmax0, __shfl_xor_sync(0xffffffffu, rmax0, 2));
        rmax1 = fmaxf(rmax1, __shfl_xor_sync(0xffffffffu, rmax1, 1));
        rmax1 = fmaxf(rmax1, __shfl_xor_sync(0xffffffffu, rmax1, 2));

        float mn0 = fmaxf(m0, rmax0), mn1 = fmaxf(m1, rmax1);
        float al0 = exp2f(m0 - mn0), al1 = exp2f(m1 - mn1);
        m0 = mn0; m1 = mn1;
        float ls0 = 0.f, ls1 = 0.f;
#pragma unroll
        for (int j = 0; j < 8; j++) {
            sacc[j][0] = exp2f(sacc[j][0] - mn0);
            sacc[j][1] = exp2f(sacc[j][1] - mn0);
            sacc[j][2] = exp2f(sacc[j][2] - mn1);
            sacc[j][3] = exp2f(sacc[j][3] - mn1);
            ls0 += sacc[j][0] + sacc[j][1];
            ls1 += sacc[j][2] + sacc[j][3];
        }
        l0 = l0 * al0 + ls0;
        l1 = l1 * al1 + ls1;
#pragma unroll
        for (int j = 0; j < 11; j++) {
            oacc[j][0] *= al0; oacc[j][1] *= al0;
            oacc[j][2] *= al1; oacc[j][3] *= al1;
        }

#pragma unroll
        for (int kk = 0; kk < 4; kk++) {
            __half2 h0 = __float22half2_rn(make_float2(sacc[2 * kk][0], sacc[2 * kk][1]));
            __half2 h1 = __float22half2_rn(make_float2(sacc[2 * kk][2], sacc[2 * kk][3]));
            __half2 h2 = __float22half2_rn(make_float2(sacc[2 * kk + 1][0], sacc[2 * kk + 1][1]));
            __half2 h3 = __float22half2_rn(make_float2(sacc[2 * kk + 1][2], sacc[2 * kk + 1][3]));
            uint32_t a0 = *(uint32_t*)&h0, a1 = *(uint32_t*)&h1;
            uint32_t a2 = *(uint32_t*)&h2, a3 = *(uint32_t*)&h3;
            int k0 = kk * 16;
            uint32_t rowaddr = vsb + (uint32_t)((k0 + lm_row) * 208);
#pragma unroll
            for (int jj = 0; jj < 6; jj++) {
                uint32_t r0, r1, r2, r3;
                uint32_t a = rowaddr + (uint32_t)((jj * 16 + lm_col) * 2);
                asm volatile(
                    "ldmatrix.sync.aligned.m8n8.x4.trans.shared.b16 {%0,%1,%2,%3}, [%4];"
                    : "=r"(r0), "=r"(r1), "=r"(r2), "=r"(r3) : "r"(a));
                mma16816(oacc[2 * jj], a0, a1, a2, a3, r0, r1);
                if (jj < 5) mma16816(oacc[2 * jj + 1], a0, a1, a2, a3, r2, r3);
            }
        }
    }

    l0 += __shfl_xor_sync(0xffffffffu, l0, 1);
    l0 += __shfl_xor_sync(0xffffffffu, l0, 2);
    l1 += __shfl_xor_sync(0xffffffffu, l1, 1);
    l1 += __shfl_xor_sync(0xffffffffu, l1, 2);
    float inv0 = 1.f / l0, inv1 = 1.f / l1;
    int b = bh >> 3;
    int row0 = rt + w * 16 + g, row1 = row0 + 8;
#pragma unroll
    for (int j = 0; j < 11; j++) {
        int d = j * 8 + 2 * tq;
        if (d < DD) {
            int m = d >> 2, c = d & 3;
            size_t o0 = ((size_t)((b << 10) + row0) * 21 + m) * 32 + (h << 2) + c;
            size_t o1 = ((size_t)((b << 10) + row1) * 21 + m) * 32 + (h << 2) + c;
            *(float2*)&g_opre[o0] = make_float2(oacc[j][0] * inv0, oacc[j][1] * inv0);
            *(float2*)&g_opre[o1] = make_float2(oacc[j][2] * inv1, oacc[j][3] * inv1);
        }
    }
}

// ---------------------------------------------------------------------------
// K6: proj, register-blocked.
// ---------------------------------------------------------------------------
__global__ void __launch_bounds__(256) k_proj(const float* __restrict__ Wp,
                                              const float* __restrict__ bp,
                                              float* __restrict__ out) {
    __shared__ float ws[32][32];
    __shared__ float bs[32];
    int t = threadIdx.x;
    for (int i = t; i < 1024; i += 256) ws[i >> 5][i & 31] = Wp[i];
    if (t < 32) bs[t] = bp[t];
    __syncthreads();
    int R = blockIdx.x * 256 + t;
    float xv[32];
    const float4* xr = (const float4*)(g_opre + (size_t)R * 32);
#pragma unroll
    for (int q = 0; q < 8; q++) {
        float4 v = xr[q];
        xv[4 * q] = v.x; xv[4 * q + 1] = v.y; xv[4 * q + 2] = v.z; xv[4 * q + 3] = v.w;
    }
#pragma unroll
    for (int half = 0; half < 2; half++) {
        float acc[16];
#pragma unroll
        for (int jj = 0; jj < 16; jj++) acc[jj] = bs[half * 16 + jj];
#pragma unroll
        for (int kk = 0; kk < 32; kk++) {
            float xvk = xv[kk];
            const float4* wr = (const float4*)&ws[kk][half * 16];
#pragma unroll
            for (int u = 0; u < 4; u++) {
                float4 wv = wr[u];
                acc[4 * u]     += xvk * wv.x;
                acc[4 * u + 1] += xvk * wv.y;
                acc[4 * u + 2] += xvk * wv.z;
                acc[4 * u + 3] += xvk * wv.w;
            }
        }
        float4* orow = (float4*)(out + (size_t)R * 32 + half * 16);
#pragma unroll
        for (int u = 0; u < 4; u++)
            orow[u] = make_float4(acc[4 * u], acc[4 * u + 1], acc[4 * u + 2], acc[4 * u + 3]);
    }
}

// ---------------------------------------------------------------------------
extern "C" void kernel_launch(void* const* d_in, const int* in_sizes, int n_in,
                              void* d_out, int out_size) {
    (void)in_sizes; (void)n_in; (void)out_size;
    const float* x   = (const float*)d_in[0];
    const float* Wq  = (const float*)d_in[1];
    const float* bq  = (const float*)d_in[2];
    const float* Wp  = (const float*)d_in[3];
    const float* bp  = (const float*)d_in[4];
    const float* Wsq = (const float*)d_in[5];
    const float* bsq = (const float*)d_in[6];
    const float* Wdw = (const float*)d_in[7];
    const float* bdw = (const float*)d_in[8];
    float* out = (float*)d_out;

    static int init_done = 0;
    static cudaStream_t s2;
    static cudaEvent_t ev0, ev1;
    if (!init_done) {
        cudaFuncSetAttribute(k_flash, cudaFuncAttributeMaxDynamicSharedMemorySize, FL_SMEM);
        cudaStreamCreateWithFlags(&s2, cudaStreamNonBlocking);
        cudaEventCreateWithFlags(&ev0, cudaEventDisableTiming);
        cudaEventCreateWithFlags(&ev1, cudaEventDisableTiming);
        init_done = 1;
    }

    // Fork: bias chain on s2 runs concurrently with qkv on the main stream.
    cudaEventRecord(ev0, 0);
    cudaStreamWaitEvent(s2, ev0, 0);
    k_x2<<<128, 256, 0, s2>>>(x, Wsq, bsq);
    k_spatial_p<<<64, 256, 0, s2>>>(Wdw);
    k_corrc<<<dim3(63, NHH), 512, 0, s2>>>(bdw);
    cudaEventRecord(ev1, s2);

    k_qkv<<<336, 256>>>(x, Wq, bq);

    // Join: flash needs q/k/v (stream order) and the bias table (ev1).
    cudaStreamWaitEvent(0, ev1, 0);
    k_flash<<<dim3(8, BH), 256, FL_SMEM>>>();
    k_proj<<<ROWS / 256, 256>>>(Wp, bp, out);
}